// round 8
// baseline (speedup 1.0000x reference)
#include <cuda_runtime.h>

// Problem constants (fixed shapes per reference)
#define KROWS 1025
#define F     8192
#define NCHUNK 128
#define ROWS_PER_CHUNK 8   // 1024/128

// Device scratch (no allocations in kernel_launch)
__device__ float g_partial[NCHUNK * F];   // 4 MB
__device__ float g_scale[F];

// Kernel 1: partial column-wise sum of |x| over rows 1..1024.
// Explicit 8-load batch so all LDG.128 are in flight before any add (MLP=8).
__global__ void relu_z_partial_abs(const float* __restrict__ x) {
    int c4    = blockIdx.x * blockDim.x + threadIdx.x;  // 0..F/4-1
    int chunk = blockIdx.y;                             // 0..127
    int r0 = 1 + chunk * ROWS_PER_CHUNK;

    const float4* p = (const float4*)(x + (size_t)r0 * F) + c4;
    const size_t st = F / 4;

    float4 v0 = p[0 * st];
    float4 v1 = p[1 * st];
    float4 v2 = p[2 * st];
    float4 v3 = p[3 * st];
    float4 v4 = p[4 * st];
    float4 v5 = p[5 * st];
    float4 v6 = p[6 * st];
    float4 v7 = p[7 * st];

    // two accumulators to shorten the dependency chain
    float4 a, b;
    a.x = fabsf(v0.x) + fabsf(v1.x);  b.x = fabsf(v2.x) + fabsf(v3.x);
    a.y = fabsf(v0.y) + fabsf(v1.y);  b.y = fabsf(v2.y) + fabsf(v3.y);
    a.z = fabsf(v0.z) + fabsf(v1.z);  b.z = fabsf(v2.z) + fabsf(v3.z);
    a.w = fabsf(v0.w) + fabsf(v1.w);  b.w = fabsf(v2.w) + fabsf(v3.w);
    a.x += fabsf(v4.x) + fabsf(v5.x); b.x += fabsf(v6.x) + fabsf(v7.x);
    a.y += fabsf(v4.y) + fabsf(v5.y); b.y += fabsf(v6.y) + fabsf(v7.y);
    a.z += fabsf(v4.z) + fabsf(v5.z); b.z += fabsf(v6.z) + fabsf(v7.z);
    a.w += fabsf(v4.w) + fabsf(v5.w); b.w += fabsf(v6.w) + fabsf(v7.w);

    float4 s;
    s.x = a.x + b.x; s.y = a.y + b.y; s.z = a.z + b.z; s.w = a.w + b.w;
    ((float4*)(g_partial + chunk * F))[c4] = s;
}

// Kernel 2: fold partials -> scale; write center row + ext diagonal float4.
__global__ void relu_z_finalize(const float* __restrict__ x,
                                const float* __restrict__ lambdas,
                                float* __restrict__ out) {
    int f = blockIdx.x * blockDim.x + threadIdx.x;
    float abssum = 0.0f;
    #pragma unroll 16
    for (int c = 0; c < NCHUNK; ++c) abssum += g_partial[c * F + f];

    float ctr = x[f];                 // x[0][f]
    float l = ctr - abssum;
    float u = ctr + abssum;
    float lam = lambdas[f];

    float pos   = (l > 0.0f) ? 1.0f : 0.0f;
    float cross = ((u > 0.0f) && (l < 0.0f)) ? 1.0f : 0.0f;
    float d     = fmaxf(-l * lam, u * (1.0f - lam));
    float scale = pos + cross * lam;
    float half  = 0.5f * cross * d;

    g_scale[f] = scale;
    out[f] = scale * ctr + half;      // center row

    // diagonal float4 of the ext block (store_all skips this slot)
    float4 dv = make_float4(0.f, 0.f, 0.f, 0.f);
    ((float*)&dv)[f & 3] = half;
    ((float4*)(out + (size_t)(KROWS + f) * F))[f >> 2] = dv;
}

// Kernel 3: ALL remaining stores in one launch.
// Unit = half a row = 1024 float4 = 256 threads x 4 float4.
//   blocks [0, 2048)      : body rows 1..1024, out = scale * x (x is L2-hot)
//   blocks [2048, 18432)  : ext rows, streaming zeros, skip diagonal float4
__global__ void __launch_bounds__(256) relu_z_store_all(
    const float* __restrict__ x, float* __restrict__ out) {
    const int b   = blockIdx.x;
    const int tid = threadIdx.x;

    if (b < 2048) {
        int r  = 1 + (b >> 1);
        int c0 = ((b & 1) << 10) + tid;
        const float4* xs = (const float4*)(x + (size_t)r * F);
        const float4* sc = (const float4*)g_scale;
        float4* os = (float4*)(out + (size_t)r * F);
        #pragma unroll
        for (int j = 0; j < 4; ++j) {
            int i = c0 + (j << 8);
            float4 v = xs[i];
            float4 s = sc[i];
            float4 o;
            o.x = s.x * v.x;
            o.y = s.y * v.y;
            o.z = s.z * v.z;
            o.w = s.w * v.w;
            __stcs(&os[i], o);             // out never re-read: bypass L2 fill
        }
    } else {
        int e     = b - 2048;
        int row   = e >> 1;
        int diag4 = row >> 2;              // float4 slot owned by finalize
        int c0    = ((e & 1) << 10) + tid;
        float4* os = (float4*)(out + (size_t)(KROWS + row) * F);
        const float4 z = make_float4(0.f, 0.f, 0.f, 0.f);

        // This thread's 4 stores are at c0 + {0,256,512,768}; diag4 collides
        // only if (diag4 & 255) == (c0 & 255). One compare, then a fast path.
        if ((diag4 & 255) != (c0 & 255) || (diag4 >> 8) != ((e & 1) << 2) + 0) {
            // fast path still needs per-j check only when low bits match; do
            // the cheap general form: hoisted flag
        }
        bool may = ((diag4 & 255) == (c0 & 255)) && ((e & 1) == ((row >> 10) & 1) || true);
        if (!((diag4 & 255) == (c0 & 255) && diag4 >= c0 && diag4 < c0 + 1024)) {
            #pragma unroll
            for (int j = 0; j < 4; ++j) __stcs(&os[c0 + (j << 8)], z);
        } else {
            #pragma unroll
            for (int j = 0; j < 4; ++j) {
                int i = c0 + (j << 8);
                if (i != diag4) __stcs(&os[i], z);
            }
        }
        (void)may;
    }
}

extern "C" void kernel_launch(void* const* d_in, const int* in_sizes, int n_in,
                              void* d_out, int out_size) {
    const float* x       = (const float*)d_in[0];
    const float* lambdas = (const float*)d_in[1];
    float* out           = (float*)d_out;

    // 1) Partial abs-sums
    {
        dim3 grid(F / 4 / 256, NCHUNK);    // 8 x 128
        relu_z_partial_abs<<<grid, 256>>>(x);
    }
    // 2) Finalize: scale, center row, ext diagonal
    relu_z_finalize<<<F / 256, 256>>>(x, lambdas, out);
    // 3) Everything else: body rows + ext zeros, one launch
    relu_z_store_all<<<2048 + 16384, 256>>>(x, out);
}